// round 17
// baseline (speedup 1.0000x reference)
#include <cuda_runtime.h>
#include <math.h>

#define H_DIM 1024
#define NAG 256
#define BTOK 8192
#define NTH 256
#define SB 64
#define TPW 8
#define LN_EPS 1e-5f
#define ALPHA_MAX 5.0f

typedef unsigned long long u64;

// ---- f32x2 packed math ----
__device__ __forceinline__ u64 fma2(u64 a, u64 b, u64 c) {
    u64 d;
    asm("fma.rn.f32x2 %0, %1, %2, %3;" : "=l"(d) : "l"(a), "l"(b), "l"(c));
    return d;
}
__device__ __forceinline__ u64 add2(u64 a, u64 b) {
    u64 d;
    asm("add.rn.f32x2 %0, %1, %2;" : "=l"(d) : "l"(a), "l"(b));
    return d;
}
__device__ __forceinline__ u64 mul2(u64 a, u64 b) {
    u64 d;
    asm("mul.rn.f32x2 %0, %1, %2;" : "=l"(d) : "l"(a), "l"(b));
    return d;
}
__device__ __forceinline__ u64 pack2(float lo, float hi) {
    u64 d;
    asm("mov.b64 %0, {%1, %2};" : "=l"(d) : "f"(lo), "f"(hi));
    return d;
}
__device__ __forceinline__ void unpack2(u64 v, float& lo, float& hi) {
    asm("mov.b64 {%0, %1}, %2;" : "=f"(lo), "=f"(hi) : "l"(v));
}

// ---- cp.async helpers ----
__device__ __forceinline__ void cp16(void* s, const void* g) {
    unsigned sa = (unsigned)__cvta_generic_to_shared(s);
    asm volatile("cp.async.cg.shared.global [%0], [%1], 16;\n" :: "r"(sa), "l"(g));
}
#define CP_COMMIT() asm volatile("cp.async.commit_group;\n" ::: "memory")
#define CP_WAIT1()  asm volatile("cp.async.wait_group 1;\n" ::: "memory")
#define CP_WAIT0()  asm volatile("cp.async.wait_group 0;\n" ::: "memory")

// SMEM layout (floats):
//   ring    3 x 6144 @ 0       (72 KB; A-stage: U 2048 + h up-to 4096; B-stage: V 4096)
//   binter  4096 f   @ 18432   (16 KB: 64 tok x 32 r duplicated u64 pairs)
//   stoksw  64 int   @ 22528
//   stoksa  256 int  @ 22592
#define STAGE_F 6144
#define OFF_BI 18432
#define OFF_TW 22528
#define OFF_TA 22592
#define SMEM_BYTES ((22592 + 256) * 4)

__device__ __forceinline__ int stage_of(int t) { return t % 3; }

__device__ __forceinline__ void issue_A_U(int t, float* smem, const float4* pu4, int tid) {
    float4* dst = (float4*)(smem + stage_of(t) * STAGE_F);
    cp16(dst + tid,       pu4 + t * 512 + tid);
    cp16(dst + 256 + tid, pu4 + t * 512 + 256 + tid);
}
__device__ __forceinline__ void issue_A_H(int t, float* smem, const float4* h4,
                                          const int* stoksw, int tid, int nb) {
    float4* dst = (float4*)(smem + stage_of(t) * STAGE_F) + 512;
    const int n4 = nb * 16;
    for (int i = tid; i < n4; i += NTH) {
        const int tok = i >> 4, cc = i & 15;
        cp16(dst + i, h4 + (size_t)stoksw[tok] * 256 + t * 16 + cc);
    }
}
__device__ __forceinline__ void issue_chunk(int t, float* smem, const float4* pu4,
                                            const float4* pv4, const float4* h4,
                                            const int* stoksw, int tid, int nb) {
    if (t < 16) {
        issue_A_U(t, smem, pu4, tid);
        issue_A_H(t, smem, h4, stoksw, tid, nb);
    } else {
        const int j = t - 16;
        float4* dst = (float4*)(smem + stage_of(t) * STAGE_F);
        #pragma unroll
        for (int i = 0; i < 4; ++i) {
            const int idx = tid + i * 256;
            const int r = idx >> 5, cc = idx & 31;
            cp16(dst + idx, pv4 + r * 256 + j * 32 + cc);
        }
    }
}

__global__ __launch_bounds__(NTH, 2)
void div_inject_kernel(const float* __restrict__ h,
                       const float* __restrict__ log_alpha,
                       const float* __restrict__ gamma,
                       const float* __restrict__ beta,
                       const float* __restrict__ pu,
                       const float* __restrict__ pv,
                       const int*   __restrict__ ids,
                       float*       __restrict__ out)
{
    extern __shared__ float smem[];
    u64* bint   = (u64*)(smem + OFF_BI);
    int* stoksw = (int*)(smem + OFF_TW);
    int* stoksa = (int*)(smem + OFF_TA);
    __shared__ int s_cnt;

    const int tid  = threadIdx.x;
    const int lane = tid & 31;
    const int wid  = tid >> 5;
    const int agent = blockIdx.x;

    const float4* pu4 = (const float4*)pu + (size_t)agent * 8192;
    const float4* pv4 = (const float4*)pv + (size_t)agent * 8192;
    const float4* h4  = (const float4*)h;
    const ulonglong2* h2 = (const ulonglong2*)h;
    ulonglong2* out2 = (ulonglong2*)out;

    // ---- prefetch U chunk 0 (group A) BEFORE the scan ----
    issue_A_U(0, smem, pu4, tid);
    CP_COMMIT();

    // ---- self-service scan ----
    if (tid == 0) s_cnt = 0;
    __syncthreads();
    {
        const int4* ids4 = (const int4*)ids;
        #pragma unroll
        for (int k = 0; k < 8; ++k) {
            const int i4 = tid + k * 256;
            int4 v = ids4[i4];
            const int b = i4 * 4;
            if ((v.x & (NAG - 1)) == agent) stoksa[atomicAdd(&s_cnt, 1)] = b;
            if ((v.y & (NAG - 1)) == agent) stoksa[atomicAdd(&s_cnt, 1)] = b + 1;
            if ((v.z & (NAG - 1)) == agent) stoksa[atomicAdd(&s_cnt, 1)] = b + 2;
            if ((v.w & (NAG - 1)) == agent) stoksa[atomicAdd(&s_cnt, 1)] = b + 3;
        }
    }
    __syncthreads();
    const int total = s_cnt;
    if (total == 0) { CP_WAIT0(); return; }

    const float alpha = fminf(expf(log_alpha[0]), ALPHA_MAX);
    const u64 al2 = pack2(alpha, alpha);

    bool first = true;
    for (int base = 0; base < total; base += SB) {
        const int nb = min(SB, total - base);

        if (tid < SB) stoksw[tid] = stoksa[base + min(tid, nb - 1)];
        __syncthreads();

        const bool gvalid = (TPW * wid) < nb;
        int  gt[TPW]; bool vd[TPW]; int tk[TPW];
        #pragma unroll
        for (int i = 0; i < TPW; ++i) {
            tk[i] = min(TPW * wid + i, nb - 1);
            vd[i] = (TPW * wid + i) < nb;
            gt[i] = stoksw[tk[i]];
        }

        // ---- prologue: chunk0 (U pre-issued on first batch) + chunk1 ----
        if (!first) { issue_A_U(0, smem, pu4, tid); }
        first = false;
        issue_A_H(0, smem, h4, stoksw, tid, nb); CP_COMMIT();
        issue_chunk(1, smem, pu4, pv4, h4, stoksw, tid, nb); CP_COMMIT();

        // ================= unified chunk loop: 0..15 = A, 16..23 = B =================
        u64 Ax[TPW], Az[TPW];
        #pragma unroll
        for (int i = 0; i < TPW; ++i) { Ax[i] = 0; Az[i] = 0; }
        float s[TPW], q[TPW];
        #pragma unroll
        for (int i = 0; i < TPW; ++i) { s[i] = 0.f; q[i] = 0.f; }

        #pragma unroll 1
        for (int t = 0; t < 24; ++t) {
            if (t < 23) { CP_WAIT1(); } else { CP_WAIT0(); }
            __syncthreads();
            if (t < 22) {
                issue_chunk(t + 2, smem, pu4, pv4, h4, stoksw, tid, nb);
                CP_COMMIT();
            }

            if (t < 16) {
                // ---- phase A chunk ----
                if (gvalid) {
                    const float* ubl = smem + stage_of(t) * STAGE_F + lane;
                    const ulonglong2* hb =
                        (const ulonglong2*)(smem + stage_of(t) * STAGE_F + 2048);

                    #pragma unroll 4
                    for (int k4 = 0; k4 < 16; ++k4) {
                        const float* up = ubl + k4 * 128;
                        u64 u01 = pack2(up[0],  up[32]);
                        u64 u23 = pack2(up[64], up[96]);
                        #pragma unroll
                        for (int i = 0; i < TPW; ++i) {
                            ulonglong2 x = hb[tk[i] * 16 + k4];
                            Ax[i] = fma2(x.x, u01, Ax[i]);
                            Az[i] = fma2(x.y, u23, Az[i]);
                        }
                    }
                }
                if (t == 15) {
                    // finalize inter -> binter (per-warp private rows)
                    if (gvalid) {
                        #pragma unroll
                        for (int i = 0; i < TPW; ++i) {
                            float f0, f1, f2, f3;
                            unpack2(Ax[i], f0, f1);
                            unpack2(Az[i], f2, f3);
                            const float iv = (f0 + f1) + (f2 + f3);
                            bint[tk[i] * 32 + lane] = pack2(iv, iv);
                        }
                    }
                    __syncwarp();
                }
            } else {
                // ---- phase B chunk ----
                const int j = t - 16;
                if (gvalid) {
                    const ulonglong2* vb =
                        (const ulonglong2*)(smem + stage_of(t) * STAGE_F);

                    u64 Px[TPW], Pz[TPW];
                    #pragma unroll
                    for (int i = 0; i < TPW; ++i) { Px[i] = 0; Pz[i] = 0; }

                    #pragma unroll 4
                    for (int rb = 0; rb < 16; ++rb) {
                        ulonglong2 v0 = vb[(2 * rb)     * 32 + lane];
                        ulonglong2 v1 = vb[(2 * rb + 1) * 32 + lane];
                        #pragma unroll
                        for (int i = 0; i < TPW; ++i) {
                            ulonglong2 bb = ((const ulonglong2*)(bint + tk[i] * 32))[rb];
                            Px[i] = fma2(bb.x, v0.x, Px[i]);
                            Pz[i] = fma2(bb.x, v0.y, Pz[i]);
                            Px[i] = fma2(bb.y, v1.x, Px[i]);
                            Pz[i] = fma2(bb.y, v1.y, Pz[i]);
                        }
                    }

                    #pragma unroll
                    for (int i = 0; i < TPW; ++i) {
                        if (!vd[i]) continue;
                        ulonglong2 hv = h2[(size_t)gt[i] * 256 + j * 32 + lane];
                        u64 dx = fma2(al2, Px[i], hv.x);
                        u64 dz = fma2(al2, Pz[i], hv.y);
                        // scalar sums (register-pressure relief)
                        float ax, bx, az, bz;
                        unpack2(dx, ax, bx);
                        unpack2(dz, az, bz);
                        s[i] += (ax + bx) + (az + bz);
                        q[i] = fmaf(ax, ax, q[i]);
                        q[i] = fmaf(bx, bx, q[i]);
                        q[i] = fmaf(az, az, q[i]);
                        q[i] = fmaf(bz, bz, q[i]);
                        ulonglong2 dd; dd.x = dx; dd.y = dz;
                        out2[(size_t)gt[i] * 256 + j * 32 + lane] = dd;
                    }
                }
            }
        }

        // ---- LN finalize + normalize ----
        if (gvalid) {
            #pragma unroll
            for (int o = 16; o > 0; o >>= 1) {
                #pragma unroll
                for (int i = 0; i < TPW; ++i) {
                    s[i] += __shfl_xor_sync(0xffffffffu, s[i], o);
                    q[i] += __shfl_xor_sync(0xffffffffu, q[i], o);
                }
            }
            const ulonglong2* g2 = (const ulonglong2*)gamma;
            const ulonglong2* b2 = (const ulonglong2*)beta;
            #pragma unroll
            for (int i = 0; i < TPW; ++i) {
                if (!vd[i]) continue;
                const float mn = s[i] * (1.0f / H_DIM);
                const float rs = rsqrtf(q[i] * (1.0f / H_DIM) - mn * mn + LN_EPS);
                const u64 nm2 = pack2(-mn, -mn);
                const u64 rs2 = pack2(rs, rs);
                ulonglong2* op = out2 + (size_t)gt[i] * 256 + lane;
                #pragma unroll
                for (int c = 0; c < 8; ++c) {
                    ulonglong2 d = op[c * 32];
                    ulonglong2 g = g2[c * 32 + lane];
                    ulonglong2 bb = b2[c * 32 + lane];
                    u64 tx = mul2(add2(d.x, nm2), rs2);
                    u64 tz = mul2(add2(d.y, nm2), rs2);
                    ulonglong2 o_;
                    o_.x = fma2(tx, g.x, bb.x);
                    o_.y = fma2(tz, g.y, bb.y);
                    op[c * 32] = o_;
                }
            }
        }
        __syncthreads();   // ring/stoksw/binter reuse safety for next batch
    }
}

extern "C" void kernel_launch(void* const* d_in, const int* in_sizes, int n_in,
                              void* d_out, int out_size)
{
    const float* h     = (const float*)d_in[0];
    const float* la    = (const float*)d_in[1];
    const float* gamma = (const float*)d_in[2];
    const float* beta  = (const float*)d_in[3];
    const float* pu    = (const float*)d_in[4];
    const float* pv    = (const float*)d_in[5];
    const int*   ids   = (const int*)d_in[6];
    float*       out   = (float*)d_out;

    cudaFuncSetAttribute(div_inject_kernel,
                         cudaFuncAttributeMaxDynamicSharedMemorySize, SMEM_BYTES);
    div_inject_kernel<<<NAG, NTH, SMEM_BYTES>>>(h, la, gamma, beta, pu, pv, ids, out);
}